// round 11
// baseline (speedup 1.0000x reference)
#include <cuda_runtime.h>
#include <cuda_bf16.h>
#include <math.h>
#include <stdint.h>

#define H  256
#define B  512
#define T  256
#define BT (B*T)

// ================= device scratch (no allocations allowed) ==================
__device__ float gM[H * H];            // M = W_oI @ W_Ih  (row n, col k), fp32
__device__ float gWCT[2 * H * H];      // (W_oI @ W_I) transposed: [j=0..511][o]
__device__ float gGT[H];               // W_oI @ W_I1T
__device__ float gGL[H];               // W_oI @ W_I1L
__device__ float gCV[H];               // W_oI @ b_I + b_oI
__device__ float gU[B * H];            // u_b
__device__ float gScores[BT];          // pre-softmax scores
// B fragments in mma register layout, lane-major:
// uint4 index = ((kt*2 + reg)*8 + g8)*32 + lane ; 4 words = 4 n-tiles.
__device__ uint4 gBhi[16 * 2 * 8 * 32];   // 128 KB
__device__ uint4 gBlo[16 * 2 * 8 * 32];   // 128 KB

// ===================== helpers ====================================
__device__ __forceinline__ uint32_t smem_u32(const void* p) {
    uint32_t a;
    asm("{ .reg .u64 t; cvta.to.shared.u64 t, %1; cvt.u32.u64 %0, t; }"
        : "=r"(a) : "l"(p));
    return a;
}
__device__ __forceinline__ float tanh_fast(float x) {
    float ax = fabsf(x);
    float t  = __expf(-2.0f * ax);
    float r  = __fdividef(1.0f - t, 1.0f + t);
    return copysignf(r, x);
}
__device__ __forceinline__ uint32_t pack_bf16x2(float lo_elem, float hi_elem) {
    __nv_bfloat162 p = __floats2bfloat162_rn(lo_elem, hi_elem); // .x = low half
    return *reinterpret_cast<uint32_t*>(&p);
}

// d += A(16x16 bf16) @ B(16x8 bf16), f32 accumulate. Plain PTX, sm_80+.
#define MMA16816(d, a0, a1, a2, a3, b0, b1)                                   \
    asm volatile("mma.sync.aligned.m16n8k16.row.col.f32.bf16.bf16.f32 "       \
        "{%0,%1,%2,%3}, {%4,%5,%6,%7}, {%8,%9}, {%0,%1,%2,%3};"               \
        : "+f"((d)[0]), "+f"((d)[1]), "+f"((d)[2]), "+f"((d)[3])              \
        : "r"(a0), "r"(a1), "r"(a2), "r"(a3), "r"(b0), "r"(b1))

#define CP_ASYNC16(dst, src) \
    asm volatile("cp.async.cg.shared.global [%0], [%1], 16;" \
                 :: "r"(dst), "l"(src) : "memory")
#define CP_COMMIT()  asm volatile("cp.async.commit_group;" ::: "memory")
#define CP_WAIT(n)   asm volatile("cp.async.wait_group %0;" :: "n"(n) : "memory")

// ================= k_vec: gGT, gGL, gCV ====================================
__global__ void k_vec(const float* __restrict__ W_oI,
                      const float* __restrict__ wT,
                      const float* __restrict__ wL,
                      const float* __restrict__ b_I,
                      const float* __restrict__ b_oI) {
    int o = threadIdx.x;
    float at = 0.f, al = 0.f, ac = 0.f;
    const float* wr = W_oI + o * H;
    for (int i = 0; i < H; i++) {
        float w = wr[i];
        at += w * wT[i];
        al += w * wL[i];
        ac += w * b_I[i];
    }
    gGT[o] = at;
    gGL[o] = al;
    gCV[o] = ac + b_oI[o];
}

// ===== k_M2: blocks 0-63: gM = W_oI@W_Ih ; blocks 64-127: gWCT =============
__global__ void k_M2(const float* __restrict__ W_oI,
                     const float* __restrict__ W_Ih,
                     const float* __restrict__ W_I) {
    __shared__ float sWo[4][H];
    int tid = threadIdx.x;
    int o0  = (blockIdx.x & 63) * 4;
    #pragma unroll
    for (int r = 0; r < 4; r++) sWo[r][tid] = W_oI[(o0 + r) * H + tid];
    __syncthreads();

    if (blockIdx.x < 64) {
        // gM[o, h] = sum_i W_oI[o,i] * W_Ih[i,h]
        float a[4] = {0.f, 0.f, 0.f, 0.f};
        for (int i = 0; i < H; i++) {
            float w = W_Ih[i * H + tid];            // coalesced
            a[0] += sWo[0][i] * w;
            a[1] += sWo[1][i] * w;
            a[2] += sWo[2][i] * w;
            a[3] += sWo[3][i] * w;
        }
        #pragma unroll
        for (int r = 0; r < 4; r++) gM[(o0 + r) * H + tid] = a[r];
    } else {
        // gWCT[j, o] = sum_i W_oI[o,i] * W_I[i,j]   (j = tid, tid+256)
        float a0[4] = {0.f, 0.f, 0.f, 0.f};
        float a1[4] = {0.f, 0.f, 0.f, 0.f};
        for (int i = 0; i < H; i++) {
            float w0 = W_I[i * (2 * H) + tid];          // coalesced
            float w1 = W_I[i * (2 * H) + tid + H];
            #pragma unroll
            for (int r = 0; r < 4; r++) {
                float s = sWo[r][i];
                a0[r] += s * w0;
                a1[r] += s * w1;
            }
        }
        #pragma unroll
        for (int r = 0; r < 4; r++) {
            gWCT[tid * H + o0 + r]       = a0[r];
            gWCT[(tid + H) * H + o0 + r] = a1[r];
        }
    }
}

// ========== k_frag: pack gM into mma B-fragment layout (hi/lo bf16) =========
__global__ void k_frag() {
    int bid  = blockIdx.x;
    int kt   = bid >> 4;
    int reg  = (bid >> 3) & 1;
    int g8   = bid & 7;
    int tid  = threadIdx.x;
    int lane = tid >> 2;
    int j    = tid & 3;

    int ntg = g8 * 4 + j;
    int n   = ntg * 8 + (lane >> 2);
    int k   = kt * 16 + reg * 8 + 2 * (lane & 3);

    float m0 = gM[n * H + k];
    float m1 = gM[n * H + k + 1];
    float h0 = __bfloat162float(__float2bfloat16(m0));
    float h1 = __bfloat162float(__float2bfloat16(m1));

    uint32_t* outh = reinterpret_cast<uint32_t*>(gBhi);
    uint32_t* outl = reinterpret_cast<uint32_t*>(gBlo);
    outh[bid * 128 + tid] = pack_bf16x2(m0, m1);
    outl[bid * 128 + tid] = pack_bf16x2(m0 - h0, m1 - h1);
}

// ========== k_u: u = h_hat @ W_C^T + cv, barrier-free, coalesced ============
// 128 blocks x 4 batches; thread = output o.
__global__ void k_u(const float* __restrict__ h_tilde,
                    const float* __restrict__ c_t) {
    __shared__ float hh[4][2 * H];    // 8 KB
    int tid = threadIdx.x;
    int b0  = blockIdx.x * 4;

    #pragma unroll
    for (int q = 0; q < 8; q++) {
        int idx = q * 256 + tid;                 // 2048 floats
        int bb = idx >> 9, j = idx & (2 * H - 1);
        hh[bb][j] = (j < H) ? h_tilde[(b0 + bb) * H + j]
                            : c_t[(b0 + bb) * H + (j - H)];
    }
    __syncthreads();

    float acc[4] = {0.f, 0.f, 0.f, 0.f};
    #pragma unroll 8
    for (int j = 0; j < 2 * H; j++) {
        float w = gWCT[j * H + tid];             // coalesced over threads
        acc[0] += hh[0][j] * w;
        acc[1] += hh[1][j] * w;
        acc[2] += hh[2][j] * w;
        acc[3] += hh[3][j] * w;
    }
    float cv = gCV[tid];
    #pragma unroll
    for (int bb = 0; bb < 4; bb++) gU[(b0 + bb) * H + tid] = acc[bb] + cv;
}

// ========== k_main_mma: bf16x3 mma.sync, TILE_M=128, smem-staged B ==========
// CTA: 128 rows x 256 cols. 8 warps = 4 row-groups (32 rows) x 2 N-halves.
// Warp: m32 x n128 (2 m-tiles x 16 n-tiles), K=256 in 16 k-slabs of 16.
#define AROW 264                       // bf16 per smem A row (256 + 8 pad)
#define SM_AHI 0                       // 128 x 528B = 67584
#define SM_ALO 67584
#define SM_B   135168                  // 2 x 16384 (hi 8K + lo 8K per buf)
#define SM_CU  167936                  // 4*256 f32 = 4096
#define SM_SC  172032                  // 128 x 2 f32 = 1024
#define SMEM_TOTAL 173056

__global__ void __launch_bounds__(256, 1)
k_main_mma(const float* __restrict__ h_hist,
           const float* __restrict__ dT,
           const float* __restrict__ dL,
           const float* __restrict__ v_t) {
    extern __shared__ char smem[];
    __nv_bfloat16* Ahi = reinterpret_cast<__nv_bfloat16*>(smem + SM_AHI);
    __nv_bfloat16* Alo = reinterpret_cast<__nv_bfloat16*>(smem + SM_ALO);
    float* cu = reinterpret_cast<float*>(smem + SM_CU);
    float* sc = reinterpret_cast<float*>(smem + SM_SC);
    const uint32_t sbB = smem_u32(smem) + SM_B;

    const int tid  = threadIdx.x;
    const int wid  = tid >> 5;
    const int lane = tid & 31;
    const int r0   = blockIdx.x * 128;    // 128 | 256 -> single batch per CTA
    const int b    = r0 >> 8;

    // constants
    cu[tid]       = gU[b * H + tid];
    cu[256 + tid] = gGT[tid];
    cu[512 + tid] = gGL[tid];
    cu[768 + tid] = v_t[tid];

    // prologue: stage B slab 0 (async) while converting A
    {
        const uint4* sh = gBhi;            // kt = 0
        const uint4* sl = gBlo;
        #pragma unroll
        for (int q = 0; q < 2; q++) {
            int idx = q * 256 + tid;       // 512 chunks each
            CP_ASYNC16(sbB + idx * 16,        sh + idx);
            CP_ASYNC16(sbB + 8192 + idx * 16, sl + idx);
        }
        CP_COMMIT();
    }

    // ---- stage A tile (128x256 fp32 -> bf16 hi/lo), coalesced float4 ----
    #pragma unroll
    for (int i = 0; i < 32; i++) {
        int f   = i * 256 + tid;           // float4 index over 128x64
        int row = f >> 6;
        int c4  = f & 63;
        float4 a = *reinterpret_cast<const float4*>(
            h_hist + (size_t)(r0 + row) * H + c4 * 4);
        float hx = __bfloat162float(__float2bfloat16(a.x));
        float hy = __bfloat162float(__float2bfloat16(a.y));
        float hz = __bfloat162float(__float2bfloat16(a.z));
        float hw = __bfloat162float(__float2bfloat16(a.w));
        uint32_t* ph = reinterpret_cast<uint32_t*>(Ahi + row * AROW + c4 * 4);
        uint32_t* pl = reinterpret_cast<uint32_t*>(Alo + row * AROW + c4 * 4);
        ph[0] = pack_bf16x2(a.x, a.y);
        ph[1] = pack_bf16x2(a.z, a.w);
        pl[0] = pack_bf16x2(a.x - hx, a.y - hy);
        pl[1] = pack_bf16x2(a.z - hz, a.w - hw);
    }

    const int rg = wid >> 1;               // row group 0..3 (32 rows)
    const int nh = wid & 1;                // N half
    const int lr = lane >> 2;              // fragment sub-row 0..7
    const int kq = 2 * (lane & 3);         // fragment k offset

    float acc[2][16][4];
    #pragma unroll
    for (int m = 0; m < 2; m++)
        #pragma unroll
        for (int i = 0; i < 16; i++)
            #pragma unroll
            for (int j = 0; j < 4; j++) acc[m][i][j] = 0.f;

    for (int kt = 0; kt < 16; kt++) {
        const int buf = kt & 1;
        // stage next slab into other buffer (freed by end-of-prev-iter sync)
        if (kt + 1 < 16) {
            const uint4* sh = gBhi + (kt + 1) * 512;
            const uint4* sl = gBlo + (kt + 1) * 512;
            uint32_t d = sbB + (buf ^ 1) * 16384;
            #pragma unroll
            for (int q = 0; q < 2; q++) {
                int idx = q * 256 + tid;
                CP_ASYNC16(d + idx * 16,        sh + idx);
                CP_ASYNC16(d + 8192 + idx * 16, sl + idx);
            }
            CP_COMMIT();
            CP_WAIT(1);                    // slab kt complete
        } else {
            CP_WAIT(0);
        }
        __syncthreads();                   // slab kt visible to all (also A on kt=0)

        const int kc = kt * 16 + kq;
        uint32_t ah[2][4], al2[2][4];
        #pragma unroll
        for (int m = 0; m < 2; m++) {
            int r = rg * 32 + m * 16 + lr;
            ah[m][0]  = *reinterpret_cast<uint32_t*>(Ahi + r * AROW + kc);
            ah[m][1]  = *reinterpret_cast<uint32_t*>(Ahi + (r + 8) * AROW + kc);
            ah[m][2]  = *reinterpret_cast<uint32_t*>(Ahi + r * AROW + kc + 8);
            ah[m][3]  = *reinterpret_cast<uint32_t*>(Ahi + (r + 8) * AROW + kc + 8);
            al2[m][0] = *reinterpret_cast<uint32_t*>(Alo + r * AROW + kc);
            al2[m][1] = *reinterpret_cast<uint32_t*>(Alo + (r + 8) * AROW + kc);
            al2[m][2] = *reinterpret_cast<uint32_t*>(Alo + r * AROW + kc + 8);
            al2[m][3] = *reinterpret_cast<uint32_t*>(Alo + (r + 8) * AROW + kc + 8);
        }

        const uint32_t bOff = SM_B + buf * 16384;
        #pragma unroll
        for (int g = 0; g < 4; g++) {
            const int g8 = nh * 4 + g;
            uint4 bh0 = *reinterpret_cast<uint4*>(smem + bOff + ((0 * 8 + g8) * 32 + lane) * 16);
            uint4 bh1 = *reinterpret_cast<uint4*>(smem + bOff + ((1 * 8 + g8) * 32 + lane) * 16);
            uint4 bl0 = *reinterpret_cast<uint4*>(smem + bOff + 8192 + ((0 * 8 + g8) * 32 + lane) * 16);
            uint4 bl1 = *reinterpret_cast<uint4*>(smem + bOff + 8192 + ((1 * 8 + g8) * 32 + lane) * 16);
            const uint32_t* h0 = reinterpret_cast<const uint32_t*>(&bh0);
            const uint32_t* h1 = reinterpret_cast<const uint32_t*>(&bh1);
            const uint32_t* l0 = reinterpret_cast<const uint32_t*>(&bl0);
            const uint32_t* l1 = reinterpret_cast<const uint32_t*>(&bl1);
            #pragma unroll
            for (int m = 0; m < 2; m++)
                #pragma unroll
                for (int j = 0; j < 4; j++) {
                    float* d = acc[m][g * 4 + j];
                    MMA16816(d, ah[m][0], ah[m][1], ah[m][2], ah[m][3], h0[j], h1[j]);
                    MMA16816(d, ah[m][0], ah[m][1], ah[m][2], ah[m][3], l0[j], l1[j]);
                    MMA16816(d, al2[m][0], al2[m][1], al2[m][2], al2[m][3], h0[j], h1[j]);
                }
        }
        __syncthreads();                   // all warps done with buf before reuse
    }

    // ---- epilogue ----
    #pragma unroll
    for (int m = 0; m < 2; m++) {
        const int r = rg * 32 + m * 16 + lr;
        const float dt0 = dT[r0 + r],     dl0 = dL[r0 + r];
        const float dt1 = dT[r0 + r + 8], dl1 = dL[r0 + r + 8];
        float s0 = 0.f, s1 = 0.f;
        #pragma unroll
        for (int nt = 0; nt < 16; nt++) {
            const int c = (nh * 16 + nt) * 8 + kq;
            float u0 = cu[c],       u1 = cu[c + 1];
            float t0 = cu[256 + c], t1 = cu[256 + c + 1];
            float l0 = cu[512 + c], l1 = cu[512 + c + 1];
            float v0 = cu[768 + c], v1 = cu[768 + c + 1];
            s0 += v0 * tanh_fast(acc[m][nt][0] + u0 + dt0 * t0 + dl0 * l0);
            s0 += v1 * tanh_fast(acc[m][nt][1] + u1 + dt0 * t1 + dl0 * l1);
            s1 += v0 * tanh_fast(acc[m][nt][2] + u0 + dt1 * t0 + dl1 * l0);
            s1 += v1 * tanh_fast(acc[m][nt][3] + u1 + dt1 * t1 + dl1 * l1);
        }
        s0 += __shfl_xor_sync(0xffffffffu, s0, 1);
        s0 += __shfl_xor_sync(0xffffffffu, s0, 2);
        s1 += __shfl_xor_sync(0xffffffffu, s1, 1);
        s1 += __shfl_xor_sync(0xffffffffu, s1, 2);
        if ((lane & 3) == 0) {
            sc[r * 2 + nh]       = s0;
            sc[(r + 8) * 2 + nh] = s1;
        }
    }
    __syncthreads();
    if (tid < 128) gScores[r0 + tid] = sc[tid * 2] + sc[tid * 2 + 1];
}

// ========== k_alpha_st: softmax over T + s_t = alpha @ h_history ============
__global__ void k_alpha_st(const float* __restrict__ h_hist,
                           float* __restrict__ out_a,
                           float* __restrict__ out_s) {
    __shared__ float al[T];
    __shared__ float redm[8];
    __shared__ float reds[8];
    __shared__ float bcast[2];
    int b = blockIdx.x, t = threadIdx.x;
    int lane = t & 31, w = t >> 5;

    float s = gScores[b * T + t];

    float m = s;
    #pragma unroll
    for (int off = 16; off; off >>= 1)
        m = fmaxf(m, __shfl_xor_sync(0xffffffffu, m, off));
    if (lane == 0) redm[w] = m;
    __syncthreads();
    if (t == 0) {
        float mm = redm[0];
        #pragma unroll
        for (int i = 1; i < 8; i++) mm = fmaxf(mm, redm[i]);
        bcast[0] = mm;
    }
    __syncthreads();
    float e = __expf(s - bcast[0]);

    float su = e;
    #pragma unroll
    for (int off = 16; off; off >>= 1)
        su += __shfl_xor_sync(0xffffffffu, su, off);
    if (lane == 0) reds[w] = su;
    __syncthreads();
    if (t == 0) {
        float ss = 0.f;
        #pragma unroll
        for (int i = 0; i < 8; i++) ss += reds[i];
        bcast[1] = 1.f / ss;
    }
    __syncthreads();

    float a = e * bcast[1];
    al[t] = a;
    out_a[b * T + t] = a;
    __syncthreads();

    float acc = 0.f;
    const float* hp = h_hist + (size_t)b * T * H + t;
    #pragma unroll 8
    for (int t2 = 0; t2 < T; t2++) acc += al[t2] * hp[t2 * H];
    out_s[b * H + t] = acc;
}

// =========================== launch ========================================
extern "C" void kernel_launch(void* const* d_in, const int* in_sizes, int n_in,
                              void* d_out, int out_size) {
    const float* h_tilde = (const float*)d_in[0];
    const float* c_t     = (const float*)d_in[1];
    const float* h_hist  = (const float*)d_in[2];
    const float* dT      = (const float*)d_in[3];
    const float* dL      = (const float*)d_in[4];
    const float* W_I     = (const float*)d_in[5];
    const float* W_Ih    = (const float*)d_in[6];
    const float* wT      = (const float*)d_in[7];
    const float* wL      = (const float*)d_in[8];
    const float* b_I     = (const float*)d_in[9];
    const float* W_oI    = (const float*)d_in[10];
    const float* b_oI    = (const float*)d_in[11];
    const float* v_t     = (const float*)d_in[12];

    float* out   = (float*)d_out;
    float* out_s = out;            // s_t   [B,H]
    float* out_a = out + B * H;    // alpha [B,T]

    cudaFuncSetAttribute(k_main_mma,
                         cudaFuncAttributeMaxDynamicSharedMemorySize,
                         SMEM_TOTAL);

    k_vec<<<1, 256>>>(W_oI, wT, wL, b_I, b_oI);
    k_M2<<<128, 256>>>(W_oI, W_Ih, W_I);
    k_frag<<<256, 128>>>();
    k_u<<<B / 4, 256>>>(h_tilde, c_t);
    k_main_mma<<<BT / 128, 256, SMEM_TOTAL>>>(h_hist, dT, dL, v_t);
    k_alpha_st<<<B, 256>>>(h_hist, out_a, out_s);
}